// round 6
// baseline (speedup 1.0000x reference)
#include <cuda_runtime.h>
#include <math.h>
#include <stdint.h>

#define B_   2
#define T_   2048
#define C_   768
#define H_   12
#define DH_  64
#define LOG2E 1.4426950408889634f
#define SK   20   // smem k-stride (16 data + 4 pad) -> conflict-free frag LDS

// Scratch (device globals — no allocation allowed)
__device__ float g_q[B_ * T_ * C_];
__device__ float g_k[B_ * T_ * C_];
__device__ float g_v[B_ * T_ * C_];
__device__ float g_att[B_ * T_ * C_];
__device__ float g_partial[B_ * H_ * T_ * 16];  // per (row, colTile) partial sum(exp)
__device__ float g_invsum[B_ * H_ * T_];        // per row: 1/sum(exp)

// ---------------------------------------------------------------------------
// tf32 helpers
// ---------------------------------------------------------------------------
__device__ __forceinline__ uint32_t f2tf(float v) {
    uint32_t r;
    asm("cvt.rna.tf32.f32 %0, %1;" : "=r"(r) : "f"(v));
    return r;
}

__device__ __forceinline__ void mma8(float4& d, const uint32_t* a, const uint32_t* b) {
    asm("mma.sync.aligned.m16n8k8.row.col.f32.tf32.tf32.f32 "
        "{%0,%1,%2,%3}, {%4,%5,%6,%7}, {%8,%9}, {%0,%1,%2,%3};"
        : "+f"(d.x), "+f"(d.y), "+f"(d.z), "+f"(d.w)
        : "r"(a[0]), "r"(a[1]), "r"(a[2]), "r"(a[3]), "r"(b[0]), "r"(b[1]));
}

// Load a [128 rows x 16 k] fp32 tile (row stride ld) into hi/lo tf32 smem.
__device__ __forceinline__ void load_tile128(const float* __restrict__ src, int ld,
                                             uint32_t (*Sh)[SK], uint32_t (*Sl)[SK],
                                             int tid) {
#pragma unroll
    for (int it = 0; it < 2; it++) {
        int idx = tid + it * 256;            // 512 float4s total
        int row = idx >> 2;
        int ko  = (idx & 3) << 2;
        float4 v = *(const float4*)(src + (size_t)row * ld + ko);
        uint32_t h;
        h = f2tf(v.x); Sh[row][ko + 0] = h; Sl[row][ko + 0] = f2tf(v.x - __uint_as_float(h));
        h = f2tf(v.y); Sh[row][ko + 1] = h; Sl[row][ko + 1] = f2tf(v.y - __uint_as_float(h));
        h = f2tf(v.z); Sh[row][ko + 2] = h; Sl[row][ko + 2] = f2tf(v.z - __uint_as_float(h));
        h = f2tf(v.w); Sh[row][ko + 3] = h; Sl[row][ko + 3] = f2tf(v.w - __uint_as_float(h));
    }
}

// ---------------------------------------------------------------------------
// Shared NT-GEMM body (3xTF32). C[m,n] = sum_k A[m*lda+k]*B[n*ldb+k]
// ---------------------------------------------------------------------------
__device__ __forceinline__ void gemm_body(const float* __restrict__ A,
                                          const float* __restrict__ Bm,
                                          float* __restrict__ C,
                                          int K, int lda, int ldb, int ldc,
                                          int m0, int n0) {
    __shared__ uint32_t Ah[128][SK], Al[128][SK], Bh[128][SK], Bl[128][SK];
    const int tid = threadIdx.x;
    const int warp = tid >> 5, lane = tid & 31;
    const int wm = (warp >> 2) * 64, wn = (warp & 3) * 32;
    const int r = lane >> 2, c = lane & 3;

    float4 acc[4][4];
#pragma unroll
    for (int i = 0; i < 4; i++)
#pragma unroll
        for (int j = 0; j < 4; j++) acc[i][j] = make_float4(0, 0, 0, 0);

    for (int k0 = 0; k0 < K; k0 += 16) {
        __syncthreads();
        load_tile128(A + (size_t)m0 * lda + k0, lda, Ah, Al, tid);
        load_tile128(Bm + (size_t)n0 * ldb + k0, ldb, Bh, Bl, tid);
        __syncthreads();
#pragma unroll
        for (int kb = 0; kb < 16; kb += 8) {
            uint32_t bh[4][2], bl[4][2];
#pragma unroll
            for (int nj = 0; nj < 4; nj++) {
                int col = wn + nj * 8 + r;
                bh[nj][0] = Bh[col][kb + c]; bh[nj][1] = Bh[col][kb + c + 4];
                bl[nj][0] = Bl[col][kb + c]; bl[nj][1] = Bl[col][kb + c + 4];
            }
#pragma unroll
            for (int mi = 0; mi < 4; mi++) {
                int row = wm + mi * 16 + r;
                uint32_t ah[4], al[4];
                ah[0] = Ah[row][kb + c];     ah[1] = Ah[row + 8][kb + c];
                ah[2] = Ah[row][kb + c + 4]; ah[3] = Ah[row + 8][kb + c + 4];
                al[0] = Al[row][kb + c];     al[1] = Al[row + 8][kb + c];
                al[2] = Al[row][kb + c + 4]; al[3] = Al[row + 8][kb + c + 4];
#pragma unroll
                for (int nj = 0; nj < 4; nj++) {
                    mma8(acc[mi][nj], al, bh[nj]);
                    mma8(acc[mi][nj], ah, bl[nj]);
                    mma8(acc[mi][nj], ah, bh[nj]);
                }
            }
        }
    }
#pragma unroll
    for (int mi = 0; mi < 4; mi++)
#pragma unroll
        for (int nj = 0; nj < 4; nj++) {
            int gm = m0 + wm + mi * 16 + r;
            int gn = n0 + wn + nj * 8 + 2 * c;
            *(float2*)&C[(size_t)gm * ldc + gn]       = make_float2(acc[mi][nj].x, acc[mi][nj].y);
            *(float2*)&C[(size_t)(gm + 8) * ldc + gn] = make_float2(acc[mi][nj].z, acc[mi][nj].w);
        }
}

// Fused QKV projection: grid (18, 32); x-blocks [0,6)->Q, [6,12)->K, [12,18)->V
__global__ void __launch_bounds__(256) gemm_qkv(const float* __restrict__ x,
                                                const float* __restrict__ wq,
                                                const float* __restrict__ wk,
                                                const float* __restrict__ wv,
                                                float* __restrict__ q,
                                                float* __restrict__ k,
                                                float* __restrict__ v) {
    const int nb = blockIdx.x;
    const int sel = nb / 6;
    const int n0 = (nb % 6) * 128;
    const int m0 = blockIdx.y * 128;
    const float* W = (sel == 0) ? wq : (sel == 1) ? wk : wv;
    float* O = (sel == 0) ? q : (sel == 1) ? k : v;
    gemm_body(x, W, O, C_, C_, C_, C_, m0, n0);
}

// Final projection: grid (6, 32)
__global__ void __launch_bounds__(256) gemm_final(const float* __restrict__ A,
                                                  const float* __restrict__ Wo,
                                                  float* __restrict__ C) {
    gemm_body(A, Wo, C, C_, C_, C_, C_, blockIdx.y * 128, blockIdx.x * 128);
}

// ---------------------------------------------------------------------------
// Scores + per-tile row partial sums of exp.
// S = 0.125*Q.K^T (masked->0). partial[(z*T+row)*16 + n0/128] = sum_j exp(S)
// grid (16, 16, 24)
// ---------------------------------------------------------------------------
__global__ void __launch_bounds__(256) scores_tc(const float* __restrict__ Q,
                                                 const float* __restrict__ Kt,
                                                 float* __restrict__ W,
                                                 float* __restrict__ partial) {
    const int z = blockIdx.z;
    const int b = z / H_, h = z % H_;
    const int m0 = blockIdx.y * 128, n0 = blockIdx.x * 128;
    const int tid = threadIdx.x;
    float* Cz = W + (size_t)z * T_ * T_;

    if (n0 > m0) {  // fully masked tile -> zeros; no partials
        const float4 zz = make_float4(0, 0, 0, 0);
        for (int idx = tid; idx < 128 * 32; idx += 256) {
            int row = idx >> 5, c4 = (idx & 31) << 2;
            *(float4*)&Cz[(size_t)(m0 + row) * T_ + n0 + c4] = zz;
        }
        return;
    }

    __shared__ uint32_t Ah[128][SK], Al[128][SK], Bh[128][SK], Bl[128][SK];
    __shared__ float spart[128][4];
    const int warp = tid >> 5, lane = tid & 31;
    const int wm = (warp >> 2) * 64, wn = (warp & 3) * 32;
    const int r = lane >> 2, c = lane & 3;
    const float* Ap = Q + (size_t)b * T_ * C_ + h * DH_;
    const float* Bp = Kt + (size_t)b * T_ * C_ + h * DH_;

    float4 acc[4][4];
#pragma unroll
    for (int i = 0; i < 4; i++)
#pragma unroll
        for (int j = 0; j < 4; j++) acc[i][j] = make_float4(0, 0, 0, 0);

#pragma unroll
    for (int k0 = 0; k0 < DH_; k0 += 16) {
        __syncthreads();
        load_tile128(Ap + (size_t)m0 * C_ + k0, C_, Ah, Al, tid);
        load_tile128(Bp + (size_t)n0 * C_ + k0, C_, Bh, Bl, tid);
        __syncthreads();
#pragma unroll
        for (int kb = 0; kb < 16; kb += 8) {
            uint32_t bh[4][2], bl[4][2];
#pragma unroll
            for (int nj = 0; nj < 4; nj++) {
                int col = wn + nj * 8 + r;
                bh[nj][0] = Bh[col][kb + c]; bh[nj][1] = Bh[col][kb + c + 4];
                bl[nj][0] = Bl[col][kb + c]; bl[nj][1] = Bl[col][kb + c + 4];
            }
#pragma unroll
            for (int mi = 0; mi < 4; mi++) {
                int row = wm + mi * 16 + r;
                uint32_t ah[4], al[4];
                ah[0] = Ah[row][kb + c];     ah[1] = Ah[row + 8][kb + c];
                ah[2] = Ah[row][kb + c + 4]; ah[3] = Ah[row + 8][kb + c + 4];
                al[0] = Al[row][kb + c];     al[1] = Al[row + 8][kb + c];
                al[2] = Al[row][kb + c + 4]; al[3] = Al[row + 8][kb + c + 4];
#pragma unroll
                for (int nj = 0; nj < 4; nj++) {
                    mma8(acc[mi][nj], al, bh[nj]);
                    mma8(acc[mi][nj], ah, bl[nj]);
                    mma8(acc[mi][nj], ah, bh[nj]);
                }
            }
        }
    }

    const bool diag = (n0 == m0);
#pragma unroll
    for (int mi = 0; mi < 4; mi++) {
        float se0 = 0.0f, se1 = 0.0f;   // exp-sums for rows gm and gm+8
        int gm = m0 + wm + mi * 16 + r;
#pragma unroll
        for (int nj = 0; nj < 4; nj++) {
            int gn = n0 + wn + nj * 8 + 2 * c;
            float x0 = 0.125f * acc[mi][nj].x, y0 = 0.125f * acc[mi][nj].y;
            float z1 = 0.125f * acc[mi][nj].z, w1 = 0.125f * acc[mi][nj].w;
            bool vx = true, vy = true, vz = true, vw = true;
            if (diag) {
                vx = (gn <= gm); vy = (gn + 1 <= gm);
                vz = (gn <= gm + 8); vw = (gn + 1 <= gm + 8);
                if (!vx) x0 = 0.0f;
                if (!vy) y0 = 0.0f;
                if (!vz) z1 = 0.0f;
                if (!vw) w1 = 0.0f;
            }
            se0 += (vx ? exp2f(x0 * LOG2E) : 0.0f) + (vy ? exp2f(y0 * LOG2E) : 0.0f);
            se1 += (vz ? exp2f(z1 * LOG2E) : 0.0f) + (vw ? exp2f(w1 * LOG2E) : 0.0f);
            *(float2*)&Cz[(size_t)gm * T_ + gn]       = make_float2(x0, y0);
            *(float2*)&Cz[(size_t)(gm + 8) * T_ + gn] = make_float2(z1, w1);
        }
        // reduce over the 4 c-lanes (lane bits 0-1)
        se0 += __shfl_xor_sync(0xffffffffu, se0, 1);
        se0 += __shfl_xor_sync(0xffffffffu, se0, 2);
        se1 += __shfl_xor_sync(0xffffffffu, se1, 1);
        se1 += __shfl_xor_sync(0xffffffffu, se1, 2);
        if (c == 0) {
            spart[wm + mi * 16 + r][warp & 3]     = se0;
            spart[wm + mi * 16 + r + 8][warp & 3] = se1;
        }
    }
    __syncthreads();
    if (tid < 128) {
        float s = spart[tid][0] + spart[tid][1] + spart[tid][2] + spart[tid][3];
        partial[((size_t)z * T_ + m0 + tid) * 16 + (n0 >> 7)] = s;
    }
}

// ---------------------------------------------------------------------------
// Reduce partials -> 1/rowsum. grid (B*H*T/256), 256 thr.
// ---------------------------------------------------------------------------
__global__ void __launch_bounds__(256) reduce_kernel(const float* __restrict__ partial,
                                                     float* __restrict__ invsum) {
    const int rg = blockIdx.x * 256 + threadIdx.x;   // [0, B*H*T)
    const int i = rg % T_;
    const int ntmax = i >> 7;
    float s = 0.0f;
    const float* p = partial + (size_t)rg * 16;
    for (int nt = 0; nt <= ntmax; nt++) s += p[nt];
    invsum[rg] = 1.0f / s;
}

// ---------------------------------------------------------------------------
// Fused normalize + weights-write + PV (3xTF32):
//   w = exp(s)*invsum (masked->0), write w, O = w @ V.
// grid (1, 16, 24), y reversed for wave balance.
// ---------------------------------------------------------------------------
__global__ void __launch_bounds__(256) pv_norm_tc(float* __restrict__ W,
                                                  const float* __restrict__ V,
                                                  float* __restrict__ O,
                                                  const float* __restrict__ invsum) {
    const int z = blockIdx.z;
    const int b = z / H_, h = z % H_;
    const int m0 = (gridDim.y - 1 - blockIdx.y) * 128;   // heavy blocks first
    const int tid = threadIdx.x;
    const int warp = tid >> 5, lane = tid & 31;
    const int wm = (warp >> 2) * 64, wn = (warp & 3) * 16;
    const int r = lane >> 2, c = lane & 3;

    float* Wz = W + (size_t)z * T_ * T_;
    const float* Vp = V + (size_t)b * T_ * C_ + h * DH_;   // V[k][n], stride C_

    __shared__ uint32_t Ah[128][SK], Al[128][SK], Bh[64][SK], Bl[64][SK];
    __shared__ float il_s[128];

    if (tid < 128) il_s[tid] = invsum[(size_t)z * T_ + m0 + tid];

    float4 acc[4][2];
#pragma unroll
    for (int i = 0; i < 4; i++)
#pragma unroll
        for (int j = 0; j < 2; j++) acc[i][j] = make_float4(0, 0, 0, 0);

    const int kmax = m0 + 128;
    for (int k0 = 0; k0 < kmax; k0 += 16) {
        __syncthreads();
        // A tile: normalized weights from raw scores; also write weights out.
#pragma unroll
        for (int it = 0; it < 2; it++) {
            int idx = tid + it * 256;
            int row = idx >> 2;
            int ko  = (idx & 3) << 2;
            float* addr = &Wz[(size_t)(m0 + row) * T_ + k0 + ko];
            float4 v = *(const float4*)addr;
            const int gm = m0 + row, gc = k0 + ko;
            const float il = il_s[row];
            float w0 = (gc     <= gm) ? exp2f(v.x * LOG2E) * il : 0.0f;
            float w1 = (gc + 1 <= gm) ? exp2f(v.y * LOG2E) * il : 0.0f;
            float w2 = (gc + 2 <= gm) ? exp2f(v.z * LOG2E) * il : 0.0f;
            float w3 = (gc + 3 <= gm) ? exp2f(v.w * LOG2E) * il : 0.0f;
            *(float4*)addr = make_float4(w0, w1, w2, w3);
            uint32_t hh;
            hh = f2tf(w0); Ah[row][ko + 0] = hh; Al[row][ko + 0] = f2tf(w0 - __uint_as_float(hh));
            hh = f2tf(w1); Ah[row][ko + 1] = hh; Al[row][ko + 1] = f2tf(w1 - __uint_as_float(hh));
            hh = f2tf(w2); Ah[row][ko + 2] = hh; Al[row][ko + 2] = f2tf(w2 - __uint_as_float(hh));
            hh = f2tf(w3); Ah[row][ko + 3] = hh; Al[row][ko + 3] = f2tf(w3 - __uint_as_float(hh));
        }
        // B tile: Bs[n][k] = V[k0+k][n]
        {
            int kr = tid >> 4;            // 0..15
            int nc = (tid & 15) << 2;     // 0..60
            float4 v = *(const float4*)(Vp + (size_t)(k0 + kr) * C_ + nc);
            uint32_t hh;
            hh = f2tf(v.x); Bh[nc + 0][kr] = hh; Bl[nc + 0][kr] = f2tf(v.x - __uint_as_float(hh));
            hh = f2tf(v.y); Bh[nc + 1][kr] = hh; Bl[nc + 1][kr] = f2tf(v.y - __uint_as_float(hh));
            hh = f2tf(v.z); Bh[nc + 2][kr] = hh; Bl[nc + 2][kr] = f2tf(v.z - __uint_as_float(hh));
            hh = f2tf(v.w); Bh[nc + 3][kr] = hh; Bl[nc + 3][kr] = f2tf(v.w - __uint_as_float(hh));
        }
        __syncthreads();
#pragma unroll
        for (int kb = 0; kb < 16; kb += 8) {
            uint32_t bh[2][2], bl[2][2];
#pragma unroll
            for (int nj = 0; nj < 2; nj++) {
                int col = wn + nj * 8 + r;
                bh[nj][0] = Bh[col][kb + c]; bh[nj][1] = Bh[col][kb + c + 4];
                bl[nj][0] = Bl[col][kb + c]; bl[nj][1] = Bl[col][kb + c + 4];
            }
#pragma unroll
            for (int mi = 0; mi < 4; mi++) {
                int row = wm + mi * 16 + r;
                uint32_t ah[4], al[4];
                ah[0] = Ah[row][kb + c];     ah[1] = Ah[row + 8][kb + c];
                ah[2] = Ah[row][kb + c + 4]; ah[3] = Ah[row + 8][kb + c + 4];
                al[0] = Al[row][kb + c];     al[1] = Al[row + 8][kb + c];
                al[2] = Al[row][kb + c + 4]; al[3] = Al[row + 8][kb + c + 4];
#pragma unroll
                for (int nj = 0; nj < 2; nj++) {
                    mma8(acc[mi][nj], al, bh[nj]);
                    mma8(acc[mi][nj], ah, bl[nj]);
                    mma8(acc[mi][nj], ah, bh[nj]);
                }
            }
        }
    }
#pragma unroll
    for (int mi = 0; mi < 4; mi++)
#pragma unroll
        for (int nj = 0; nj < 2; nj++) {
            int gm = m0 + wm + mi * 16 + r;
            int gn = wn + nj * 8 + 2 * c;
            *(float2*)&O[(size_t)(b * T_ + gm) * C_ + h * DH_ + gn] =
                make_float2(acc[mi][nj].x, acc[mi][nj].y);
            *(float2*)&O[(size_t)(b * T_ + gm + 8) * C_ + h * DH_ + gn] =
                make_float2(acc[mi][nj].z, acc[mi][nj].w);
        }
}

// ---------------------------------------------------------------------------
extern "C" void kernel_launch(void* const* d_in, const int* in_sizes, int n_in,
                              void* d_out, int out_size) {
    const float* x   = (const float*)d_in[0];
    const float* w_q = (const float*)d_in[1];
    const float* w_k = (const float*)d_in[2];
    const float* w_v = (const float*)d_in[3];
    const float* w_o = (const float*)d_in[4];

    float* qp; cudaGetSymbolAddress((void**)&qp, g_q);
    float* kp; cudaGetSymbolAddress((void**)&kp, g_k);
    float* vp; cudaGetSymbolAddress((void**)&vp, g_v);
    float* ap; cudaGetSymbolAddress((void**)&ap, g_att);
    float* pp; cudaGetSymbolAddress((void**)&pp, g_partial);
    float* ip; cudaGetSymbolAddress((void**)&ip, g_invsum);

    float* final_out = (float*)d_out;                       // [B,T,C]
    float* w_out = (float*)d_out + (size_t)B_ * T_ * C_;    // [B,H,T,T]

    const dim3 blk(256);

    gemm_qkv<<<dim3(18, 32), blk>>>(x, w_q, w_k, w_v, qp, kp, vp);

    scores_tc<<<dim3(T_ / 128, T_ / 128, B_ * H_), blk>>>(qp, kp, w_out, pp);

    reduce_kernel<<<(B_ * H_ * T_) / 256, blk>>>(pp, ip);

    pv_norm_tc<<<dim3(1, T_ / 128, B_ * H_), blk>>>(w_out, vp, ap, ip);

    gemm_final<<<dim3(6, 32), blk>>>(ap, w_o, final_out);
}

// round 7
// speedup vs baseline: 1.0002x; 1.0002x over previous
#include <cuda_runtime.h>
#include <math.h>
#include <stdint.h>

#define B_   2
#define T_   2048
#define C_   768
#define H_   12
#define DH_  64
#define LOG2E 1.4426950408889634f
#define SK   20   // smem k-stride (16 data + 4 pad) -> conflict-free frag LDS

// Scratch (device globals — no allocation allowed)
__device__ float g_q[B_ * T_ * C_];
__device__ float g_k[B_ * T_ * C_];
__device__ float g_v[B_ * T_ * C_];
__device__ float g_att[B_ * T_ * C_];
__device__ float g_partial[B_ * H_ * T_ * 16];  // per (row, colTile) partial sum(exp)
__device__ float g_invsum[B_ * H_ * T_];        // per row: 1/sum(exp)

// ---------------------------------------------------------------------------
// tf32 helpers
// ---------------------------------------------------------------------------
__device__ __forceinline__ uint32_t f2tf(float v) {
    uint32_t r;
    asm("cvt.rna.tf32.f32 %0, %1;" : "=r"(r) : "f"(v));
    return r;
}

__device__ __forceinline__ void mma8(float4& d, const uint32_t* a, const uint32_t* b) {
    asm("mma.sync.aligned.m16n8k8.row.col.f32.tf32.tf32.f32 "
        "{%0,%1,%2,%3}, {%4,%5,%6,%7}, {%8,%9}, {%0,%1,%2,%3};"
        : "+f"(d.x), "+f"(d.y), "+f"(d.z), "+f"(d.w)
        : "r"(a[0]), "r"(a[1]), "r"(a[2]), "r"(a[3]), "r"(b[0]), "r"(b[1]));
}

// Load a [128 rows x 16 k] fp32 tile (row stride ld) into hi/lo tf32 smem.
__device__ __forceinline__ void load_tile128(const float* __restrict__ src, int ld,
                                             uint32_t (*Sh)[SK], uint32_t (*Sl)[SK],
                                             int tid) {
#pragma unroll
    for (int it = 0; it < 2; it++) {
        int idx = tid + it * 256;            // 512 float4s total
        int row = idx >> 2;
        int ko  = (idx & 3) << 2;
        float4 v = *(const float4*)(src + (size_t)row * ld + ko);
        uint32_t h;
        h = f2tf(v.x); Sh[row][ko + 0] = h; Sl[row][ko + 0] = f2tf(v.x - __uint_as_float(h));
        h = f2tf(v.y); Sh[row][ko + 1] = h; Sl[row][ko + 1] = f2tf(v.y - __uint_as_float(h));
        h = f2tf(v.z); Sh[row][ko + 2] = h; Sl[row][ko + 2] = f2tf(v.z - __uint_as_float(h));
        h = f2tf(v.w); Sh[row][ko + 3] = h; Sl[row][ko + 3] = f2tf(v.w - __uint_as_float(h));
    }
}

// ---------------------------------------------------------------------------
// Shared NT-GEMM body (3xTF32). C[m,n] = sum_k A[m*lda+k]*B[n*ldb+k]
// ---------------------------------------------------------------------------
__device__ __forceinline__ void gemm_body(const float* __restrict__ A,
                                          const float* __restrict__ Bm,
                                          float* __restrict__ C,
                                          int K, int lda, int ldb, int ldc,
                                          int m0, int n0) {
    __shared__ uint32_t Ah[128][SK], Al[128][SK], Bh[128][SK], Bl[128][SK];
    const int tid = threadIdx.x;
    const int warp = tid >> 5, lane = tid & 31;
    const int wm = (warp >> 2) * 64, wn = (warp & 3) * 32;
    const int r = lane >> 2, c = lane & 3;

    float4 acc[4][4];
#pragma unroll
    for (int i = 0; i < 4; i++)
#pragma unroll
        for (int j = 0; j < 4; j++) acc[i][j] = make_float4(0, 0, 0, 0);

    for (int k0 = 0; k0 < K; k0 += 16) {
        __syncthreads();
        load_tile128(A + (size_t)m0 * lda + k0, lda, Ah, Al, tid);
        load_tile128(Bm + (size_t)n0 * ldb + k0, ldb, Bh, Bl, tid);
        __syncthreads();
#pragma unroll
        for (int kb = 0; kb < 16; kb += 8) {
            uint32_t bh[4][2], bl[4][2];
#pragma unroll
            for (int nj = 0; nj < 4; nj++) {
                int col = wn + nj * 8 + r;
                bh[nj][0] = Bh[col][kb + c]; bh[nj][1] = Bh[col][kb + c + 4];
                bl[nj][0] = Bl[col][kb + c]; bl[nj][1] = Bl[col][kb + c + 4];
            }
#pragma unroll
            for (int mi = 0; mi < 4; mi++) {
                int row = wm + mi * 16 + r;
                uint32_t ah[4], al[4];
                ah[0] = Ah[row][kb + c];     ah[1] = Ah[row + 8][kb + c];
                ah[2] = Ah[row][kb + c + 4]; ah[3] = Ah[row + 8][kb + c + 4];
                al[0] = Al[row][kb + c];     al[1] = Al[row + 8][kb + c];
                al[2] = Al[row][kb + c + 4]; al[3] = Al[row + 8][kb + c + 4];
#pragma unroll
                for (int nj = 0; nj < 4; nj++) {
                    mma8(acc[mi][nj], al, bh[nj]);
                    mma8(acc[mi][nj], ah, bl[nj]);
                    mma8(acc[mi][nj], ah, bh[nj]);
                }
            }
        }
    }
#pragma unroll
    for (int mi = 0; mi < 4; mi++)
#pragma unroll
        for (int nj = 0; nj < 4; nj++) {
            int gm = m0 + wm + mi * 16 + r;
            int gn = n0 + wn + nj * 8 + 2 * c;
            *(float2*)&C[(size_t)gm * ldc + gn]       = make_float2(acc[mi][nj].x, acc[mi][nj].y);
            *(float2*)&C[(size_t)(gm + 8) * ldc + gn] = make_float2(acc[mi][nj].z, acc[mi][nj].w);
        }
}

// Fused QKV projection: grid (18, 32); x-blocks [0,6)->Q, [6,12)->K, [12,18)->V
__global__ void __launch_bounds__(256) gemm_qkv(const float* __restrict__ x,
                                                const float* __restrict__ wq,
                                                const float* __restrict__ wk,
                                                const float* __restrict__ wv,
                                                float* __restrict__ q,
                                                float* __restrict__ k,
                                                float* __restrict__ v) {
    const int nb = blockIdx.x;
    const int sel = nb / 6;
    const int n0 = (nb % 6) * 128;
    const int m0 = blockIdx.y * 128;
    const float* W = (sel == 0) ? wq : (sel == 1) ? wk : wv;
    float* O = (sel == 0) ? q : (sel == 1) ? k : v;
    gemm_body(x, W, O, C_, C_, C_, C_, m0, n0);
}

// Final projection: grid (6, 32)
__global__ void __launch_bounds__(256) gemm_final(const float* __restrict__ A,
                                                  const float* __restrict__ Wo,
                                                  float* __restrict__ C) {
    gemm_body(A, Wo, C, C_, C_, C_, C_, blockIdx.y * 128, blockIdx.x * 128);
}

// ---------------------------------------------------------------------------
// Scores + per-tile row partial sums of exp.
// S = 0.125*Q.K^T (masked->0). partial[(z*T+row)*16 + n0/128] = sum_j exp(S)
// grid (16, 16, 24)
// ---------------------------------------------------------------------------
__global__ void __launch_bounds__(256) scores_tc(const float* __restrict__ Q,
                                                 const float* __restrict__ Kt,
                                                 float* __restrict__ W,
                                                 float* __restrict__ partial) {
    const int z = blockIdx.z;
    const int b = z / H_, h = z % H_;
    const int m0 = blockIdx.y * 128, n0 = blockIdx.x * 128;
    const int tid = threadIdx.x;
    float* Cz = W + (size_t)z * T_ * T_;

    if (n0 > m0) {  // fully masked tile -> zeros; no partials
        const float4 zz = make_float4(0, 0, 0, 0);
        for (int idx = tid; idx < 128 * 32; idx += 256) {
            int row = idx >> 5, c4 = (idx & 31) << 2;
            *(float4*)&Cz[(size_t)(m0 + row) * T_ + n0 + c4] = zz;
        }
        return;
    }

    __shared__ uint32_t Ah[128][SK], Al[128][SK], Bh[128][SK], Bl[128][SK];
    __shared__ float spart[128][4];
    const int warp = tid >> 5, lane = tid & 31;
    const int wm = (warp >> 2) * 64, wn = (warp & 3) * 32;
    const int r = lane >> 2, c = lane & 3;
    const float* Ap = Q + (size_t)b * T_ * C_ + h * DH_;
    const float* Bp = Kt + (size_t)b * T_ * C_ + h * DH_;

    float4 acc[4][4];
#pragma unroll
    for (int i = 0; i < 4; i++)
#pragma unroll
        for (int j = 0; j < 4; j++) acc[i][j] = make_float4(0, 0, 0, 0);

#pragma unroll
    for (int k0 = 0; k0 < DH_; k0 += 16) {
        __syncthreads();
        load_tile128(Ap + (size_t)m0 * C_ + k0, C_, Ah, Al, tid);
        load_tile128(Bp + (size_t)n0 * C_ + k0, C_, Bh, Bl, tid);
        __syncthreads();
#pragma unroll
        for (int kb = 0; kb < 16; kb += 8) {
            uint32_t bh[4][2], bl[4][2];
#pragma unroll
            for (int nj = 0; nj < 4; nj++) {
                int col = wn + nj * 8 + r;
                bh[nj][0] = Bh[col][kb + c]; bh[nj][1] = Bh[col][kb + c + 4];
                bl[nj][0] = Bl[col][kb + c]; bl[nj][1] = Bl[col][kb + c + 4];
            }
#pragma unroll
            for (int mi = 0; mi < 4; mi++) {
                int row = wm + mi * 16 + r;
                uint32_t ah[4], al[4];
                ah[0] = Ah[row][kb + c];     ah[1] = Ah[row + 8][kb + c];
                ah[2] = Ah[row][kb + c + 4]; ah[3] = Ah[row + 8][kb + c + 4];
                al[0] = Al[row][kb + c];     al[1] = Al[row + 8][kb + c];
                al[2] = Al[row][kb + c + 4]; al[3] = Al[row + 8][kb + c + 4];
#pragma unroll
                for (int nj = 0; nj < 4; nj++) {
                    mma8(acc[mi][nj], al, bh[nj]);
                    mma8(acc[mi][nj], ah, bl[nj]);
                    mma8(acc[mi][nj], ah, bh[nj]);
                }
            }
        }
    }

    const bool diag = (n0 == m0);
#pragma unroll
    for (int mi = 0; mi < 4; mi++) {
        float se0 = 0.0f, se1 = 0.0f;   // exp-sums for rows gm and gm+8
        int gm = m0 + wm + mi * 16 + r;
#pragma unroll
        for (int nj = 0; nj < 4; nj++) {
            int gn = n0 + wn + nj * 8 + 2 * c;
            float x0 = 0.125f * acc[mi][nj].x, y0 = 0.125f * acc[mi][nj].y;
            float z1 = 0.125f * acc[mi][nj].z, w1 = 0.125f * acc[mi][nj].w;
            bool vx = true, vy = true, vz = true, vw = true;
            if (diag) {
                vx = (gn <= gm); vy = (gn + 1 <= gm);
                vz = (gn <= gm + 8); vw = (gn + 1 <= gm + 8);
                if (!vx) x0 = 0.0f;
                if (!vy) y0 = 0.0f;
                if (!vz) z1 = 0.0f;
                if (!vw) w1 = 0.0f;
            }
            se0 += (vx ? exp2f(x0 * LOG2E) : 0.0f) + (vy ? exp2f(y0 * LOG2E) : 0.0f);
            se1 += (vz ? exp2f(z1 * LOG2E) : 0.0f) + (vw ? exp2f(w1 * LOG2E) : 0.0f);
            *(float2*)&Cz[(size_t)gm * T_ + gn]       = make_float2(x0, y0);
            *(float2*)&Cz[(size_t)(gm + 8) * T_ + gn] = make_float2(z1, w1);
        }
        // reduce over the 4 c-lanes (lane bits 0-1)
        se0 += __shfl_xor_sync(0xffffffffu, se0, 1);
        se0 += __shfl_xor_sync(0xffffffffu, se0, 2);
        se1 += __shfl_xor_sync(0xffffffffu, se1, 1);
        se1 += __shfl_xor_sync(0xffffffffu, se1, 2);
        if (c == 0) {
            spart[wm + mi * 16 + r][warp & 3]     = se0;
            spart[wm + mi * 16 + r + 8][warp & 3] = se1;
        }
    }
    __syncthreads();
    if (tid < 128) {
        float s = spart[tid][0] + spart[tid][1] + spart[tid][2] + spart[tid][3];
        partial[((size_t)z * T_ + m0 + tid) * 16 + (n0 >> 7)] = s;
    }
}

// ---------------------------------------------------------------------------
// Reduce partials -> 1/rowsum. grid (B*H*T/256), 256 thr.
// ---------------------------------------------------------------------------
__global__ void __launch_bounds__(256) reduce_kernel(const float* __restrict__ partial,
                                                     float* __restrict__ invsum) {
    const int rg = blockIdx.x * 256 + threadIdx.x;   // [0, B*H*T)
    const int i = rg % T_;
    const int ntmax = i >> 7;
    float s = 0.0f;
    const float* p = partial + (size_t)rg * 16;
    for (int nt = 0; nt <= ntmax; nt++) s += p[nt];
    invsum[rg] = 1.0f / s;
}

// ---------------------------------------------------------------------------
// Fused normalize + weights-write + PV (3xTF32):
//   w = exp(s)*invsum (masked->0), write w, O = w @ V.
// grid (1, 16, 24), y reversed for wave balance.
// ---------------------------------------------------------------------------
__global__ void __launch_bounds__(256) pv_norm_tc(float* __restrict__ W,
                                                  const float* __restrict__ V,
                                                  float* __restrict__ O,
                                                  const float* __restrict__ invsum) {
    const int z = blockIdx.z;
    const int b = z / H_, h = z % H_;
    const int m0 = (gridDim.y - 1 - blockIdx.y) * 128;   // heavy blocks first
    const int tid = threadIdx.x;
    const int warp = tid >> 5, lane = tid & 31;
    const int wm = (warp >> 2) * 64, wn = (warp & 3) * 16;
    const int r = lane >> 2, c = lane & 3;

    float* Wz = W + (size_t)z * T_ * T_;
    const float* Vp = V + (size_t)b * T_ * C_ + h * DH_;   // V[k][n], stride C_

    __shared__ uint32_t Ah[128][SK], Al[128][SK], Bh[64][SK], Bl[64][SK];
    __shared__ float il_s[128];

    if (tid < 128) il_s[tid] = invsum[(size_t)z * T_ + m0 + tid];

    float4 acc[4][2];
#pragma unroll
    for (int i = 0; i < 4; i++)
#pragma unroll
        for (int j = 0; j < 2; j++) acc[i][j] = make_float4(0, 0, 0, 0);

    const int kmax = m0 + 128;
    for (int k0 = 0; k0 < kmax; k0 += 16) {
        __syncthreads();
        // A tile: normalized weights from raw scores; also write weights out.
#pragma unroll
        for (int it = 0; it < 2; it++) {
            int idx = tid + it * 256;
            int row = idx >> 2;
            int ko  = (idx & 3) << 2;
            float* addr = &Wz[(size_t)(m0 + row) * T_ + k0 + ko];
            float4 v = *(const float4*)addr;
            const int gm = m0 + row, gc = k0 + ko;
            const float il = il_s[row];
            float w0 = (gc     <= gm) ? exp2f(v.x * LOG2E) * il : 0.0f;
            float w1 = (gc + 1 <= gm) ? exp2f(v.y * LOG2E) * il : 0.0f;
            float w2 = (gc + 2 <= gm) ? exp2f(v.z * LOG2E) * il : 0.0f;
            float w3 = (gc + 3 <= gm) ? exp2f(v.w * LOG2E) * il : 0.0f;
            *(float4*)addr = make_float4(w0, w1, w2, w3);
            uint32_t hh;
            hh = f2tf(w0); Ah[row][ko + 0] = hh; Al[row][ko + 0] = f2tf(w0 - __uint_as_float(hh));
            hh = f2tf(w1); Ah[row][ko + 1] = hh; Al[row][ko + 1] = f2tf(w1 - __uint_as_float(hh));
            hh = f2tf(w2); Ah[row][ko + 2] = hh; Al[row][ko + 2] = f2tf(w2 - __uint_as_float(hh));
            hh = f2tf(w3); Ah[row][ko + 3] = hh; Al[row][ko + 3] = f2tf(w3 - __uint_as_float(hh));
        }
        // B tile: Bs[n][k] = V[k0+k][n]
        {
            int kr = tid >> 4;            // 0..15
            int nc = (tid & 15) << 2;     // 0..60
            float4 v = *(const float4*)(Vp + (size_t)(k0 + kr) * C_ + nc);
            uint32_t hh;
            hh = f2tf(v.x); Bh[nc + 0][kr] = hh; Bl[nc + 0][kr] = f2tf(v.x - __uint_as_float(hh));
            hh = f2tf(v.y); Bh[nc + 1][kr] = hh; Bl[nc + 1][kr] = f2tf(v.y - __uint_as_float(hh));
            hh = f2tf(v.z); Bh[nc + 2][kr] = hh; Bl[nc + 2][kr] = f2tf(v.z - __uint_as_float(hh));
            hh = f2tf(v.w); Bh[nc + 3][kr] = hh; Bl[nc + 3][kr] = f2tf(v.w - __uint_as_float(hh));
        }
        __syncthreads();
#pragma unroll
        for (int kb = 0; kb < 16; kb += 8) {
            uint32_t bh[2][2], bl[2][2];
#pragma unroll
            for (int nj = 0; nj < 2; nj++) {
                int col = wn + nj * 8 + r;
                bh[nj][0] = Bh[col][kb + c]; bh[nj][1] = Bh[col][kb + c + 4];
                bl[nj][0] = Bl[col][kb + c]; bl[nj][1] = Bl[col][kb + c + 4];
            }
#pragma unroll
            for (int mi = 0; mi < 4; mi++) {
                int row = wm + mi * 16 + r;
                uint32_t ah[4], al[4];
                ah[0] = Ah[row][kb + c];     ah[1] = Ah[row + 8][kb + c];
                ah[2] = Ah[row][kb + c + 4]; ah[3] = Ah[row + 8][kb + c + 4];
                al[0] = Al[row][kb + c];     al[1] = Al[row + 8][kb + c];
                al[2] = Al[row][kb + c + 4]; al[3] = Al[row + 8][kb + c + 4];
#pragma unroll
                for (int nj = 0; nj < 2; nj++) {
                    mma8(acc[mi][nj], al, bh[nj]);
                    mma8(acc[mi][nj], ah, bl[nj]);
                    mma8(acc[mi][nj], ah, bh[nj]);
                }
            }
        }
    }
#pragma unroll
    for (int mi = 0; mi < 4; mi++)
#pragma unroll
        for (int nj = 0; nj < 2; nj++) {
            int gm = m0 + wm + mi * 16 + r;
            int gn = wn + nj * 8 + 2 * c;
            *(float2*)&O[(size_t)(b * T_ + gm) * C_ + h * DH_ + gn] =
                make_float2(acc[mi][nj].x, acc[mi][nj].y);
            *(float2*)&O[(size_t)(b * T_ + gm + 8) * C_ + h * DH_ + gn] =
                make_float2(acc[mi][nj].z, acc[mi][nj].w);
        }
}

// ---------------------------------------------------------------------------
extern "C" void kernel_launch(void* const* d_in, const int* in_sizes, int n_in,
                              void* d_out, int out_size) {
    const float* x   = (const float*)d_in[0];
    const float* w_q = (const float*)d_in[1];
    const float* w_k = (const float*)d_in[2];
    const float* w_v = (const float*)d_in[3];
    const float* w_o = (const float*)d_in[4];

    float* qp; cudaGetSymbolAddress((void**)&qp, g_q);
    float* kp; cudaGetSymbolAddress((void**)&kp, g_k);
    float* vp; cudaGetSymbolAddress((void**)&vp, g_v);
    float* ap; cudaGetSymbolAddress((void**)&ap, g_att);
    float* pp; cudaGetSymbolAddress((void**)&pp, g_partial);
    float* ip; cudaGetSymbolAddress((void**)&ip, g_invsum);

    float* final_out = (float*)d_out;                       // [B,T,C]
    float* w_out = (float*)d_out + (size_t)B_ * T_ * C_;    // [B,H,T,T]

    const dim3 blk(256);

    gemm_qkv<<<dim3(18, 32), blk>>>(x, w_q, w_k, w_v, qp, kp, vp);

    scores_tc<<<dim3(T_ / 128, T_ / 128, B_ * H_), blk>>>(qp, kp, w_out, pp);

    reduce_kernel<<<(B_ * H_ * T_) / 256, blk>>>(pp, ip);

    pv_norm_tc<<<dim3(1, T_ / 128, B_ * H_), blk>>>(w_out, vp, ap, ip);

    gemm_final<<<dim3(6, 32), blk>>>(ap, w_o, final_out);
}

// round 8
// speedup vs baseline: 1.1130x; 1.1128x over previous
#include <cuda_runtime.h>
#include <math.h>
#include <stdint.h>

#define B_   2
#define T_   2048
#define C_   768
#define H_   12
#define DH_  64
#define LOG2E 1.4426950408889634f
#define SK   20   // smem k-stride (16 data + 4 pad) -> conflict-free frag LDS

// Scratch (device globals — no allocation allowed)
__device__ float g_q[B_ * T_ * C_];
__device__ float g_k[B_ * T_ * C_];
__device__ float g_v[B_ * T_ * C_];
__device__ float g_att[B_ * T_ * C_];
__device__ float g_partial[B_ * H_ * T_ * 16];      // per (row, colTile) partial sum(exp)
__device__ float g_invsum[B_ * H_ * T_];            // per row: 1/sum(exp)
__device__ float g_pvpart[B_ * H_ * 16 * 4 * 128 * DH_];  // pv k-split partials

// ---------------------------------------------------------------------------
__device__ __forceinline__ uint32_t f2tf(float v) {
    uint32_t r;
    asm("cvt.rna.tf32.f32 %0, %1;" : "=r"(r) : "f"(v));
    return r;
}

__device__ __forceinline__ void mma8(float4& d, const uint32_t* a, const uint32_t* b) {
    asm("mma.sync.aligned.m16n8k8.row.col.f32.tf32.tf32.f32 "
        "{%0,%1,%2,%3}, {%4,%5,%6,%7}, {%8,%9}, {%0,%1,%2,%3};"
        : "+f"(d.x), "+f"(d.y), "+f"(d.z), "+f"(d.w)
        : "r"(a[0]), "r"(a[1]), "r"(a[2]), "r"(a[3]), "r"(b[0]), "r"(b[1]));
}

__device__ __forceinline__ void load_tile128(const float* __restrict__ src, int ld,
                                             uint32_t (*Sh)[SK], uint32_t (*Sl)[SK],
                                             int tid) {
#pragma unroll
    for (int it = 0; it < 2; it++) {
        int idx = tid + it * 256;
        int row = idx >> 2;
        int ko  = (idx & 3) << 2;
        float4 v = *(const float4*)(src + (size_t)row * ld + ko);
        uint32_t h;
        h = f2tf(v.x); Sh[row][ko + 0] = h; Sl[row][ko + 0] = f2tf(v.x - __uint_as_float(h));
        h = f2tf(v.y); Sh[row][ko + 1] = h; Sl[row][ko + 1] = f2tf(v.y - __uint_as_float(h));
        h = f2tf(v.z); Sh[row][ko + 2] = h; Sl[row][ko + 2] = f2tf(v.z - __uint_as_float(h));
        h = f2tf(v.w); Sh[row][ko + 3] = h; Sl[row][ko + 3] = f2tf(v.w - __uint_as_float(h));
    }
}

// ---------------------------------------------------------------------------
// Shared NT-GEMM body (3xTF32), 128x128 tile.
// ---------------------------------------------------------------------------
__device__ __forceinline__ void gemm_body(const float* __restrict__ A,
                                          const float* __restrict__ Bm,
                                          float* __restrict__ C,
                                          int K, int lda, int ldb, int ldc,
                                          int m0, int n0) {
    __shared__ uint32_t Ah[128][SK], Al[128][SK], Bh[128][SK], Bl[128][SK];
    const int tid = threadIdx.x;
    const int warp = tid >> 5, lane = tid & 31;
    const int wm = (warp >> 2) * 64, wn = (warp & 3) * 32;
    const int r = lane >> 2, c = lane & 3;

    float4 acc[4][4];
#pragma unroll
    for (int i = 0; i < 4; i++)
#pragma unroll
        for (int j = 0; j < 4; j++) acc[i][j] = make_float4(0, 0, 0, 0);

    for (int k0 = 0; k0 < K; k0 += 16) {
        __syncthreads();
        load_tile128(A + (size_t)m0 * lda + k0, lda, Ah, Al, tid);
        load_tile128(Bm + (size_t)n0 * ldb + k0, ldb, Bh, Bl, tid);
        __syncthreads();
#pragma unroll
        for (int kb = 0; kb < 16; kb += 8) {
            uint32_t bh[4][2], bl[4][2];
#pragma unroll
            for (int nj = 0; nj < 4; nj++) {
                int col = wn + nj * 8 + r;
                bh[nj][0] = Bh[col][kb + c]; bh[nj][1] = Bh[col][kb + c + 4];
                bl[nj][0] = Bl[col][kb + c]; bl[nj][1] = Bl[col][kb + c + 4];
            }
#pragma unroll
            for (int mi = 0; mi < 4; mi++) {
                int row = wm + mi * 16 + r;
                uint32_t ah[4], al[4];
                ah[0] = Ah[row][kb + c];     ah[1] = Ah[row + 8][kb + c];
                ah[2] = Ah[row][kb + c + 4]; ah[3] = Ah[row + 8][kb + c + 4];
                al[0] = Al[row][kb + c];     al[1] = Al[row + 8][kb + c];
                al[2] = Al[row][kb + c + 4]; al[3] = Al[row + 8][kb + c + 4];
#pragma unroll
                for (int nj = 0; nj < 4; nj++) {
                    mma8(acc[mi][nj], al, bh[nj]);
                    mma8(acc[mi][nj], ah, bl[nj]);
                    mma8(acc[mi][nj], ah, bh[nj]);
                }
            }
        }
    }
#pragma unroll
    for (int mi = 0; mi < 4; mi++)
#pragma unroll
        for (int nj = 0; nj < 4; nj++) {
            int gm = m0 + wm + mi * 16 + r;
            int gn = n0 + wn + nj * 8 + 2 * c;
            *(float2*)&C[(size_t)gm * ldc + gn]       = make_float2(acc[mi][nj].x, acc[mi][nj].y);
            *(float2*)&C[(size_t)(gm + 8) * ldc + gn] = make_float2(acc[mi][nj].z, acc[mi][nj].w);
        }
}

// Fused QKV projection: grid (18, 32)
__global__ void __launch_bounds__(256) gemm_qkv(const float* __restrict__ x,
                                                const float* __restrict__ wq,
                                                const float* __restrict__ wk,
                                                const float* __restrict__ wv,
                                                float* __restrict__ q,
                                                float* __restrict__ k,
                                                float* __restrict__ v) {
    const int nb = blockIdx.x;
    const int sel = nb / 6;
    const int n0 = (nb % 6) * 128;
    const int m0 = blockIdx.y * 128;
    const float* W = (sel == 0) ? wq : (sel == 1) ? wk : wv;
    float* O = (sel == 0) ? q : (sel == 1) ? k : v;
    gemm_body(x, W, O, C_, C_, C_, C_, m0, n0);
}

// Final projection: grid (6, 32)
__global__ void __launch_bounds__(256) gemm_final(const float* __restrict__ A,
                                                  const float* __restrict__ Wo,
                                                  float* __restrict__ C) {
    gemm_body(A, Wo, C, C_, C_, C_, C_, blockIdx.y * 128, blockIdx.x * 128);
}

// ---------------------------------------------------------------------------
// Scores -> store UNNORMALIZED exp(0.125*QK) (masked->0) + row partial sums.
// grid (16, 16, 24)
// ---------------------------------------------------------------------------
__global__ void __launch_bounds__(256) scores_tc(const float* __restrict__ Q,
                                                 const float* __restrict__ Kt,
                                                 float* __restrict__ W,
                                                 float* __restrict__ partial) {
    const int z = blockIdx.z;
    const int b = z / H_, h = z % H_;
    const int m0 = blockIdx.y * 128, n0 = blockIdx.x * 128;
    const int tid = threadIdx.x;
    float* Cz = W + (size_t)z * T_ * T_;

    if (n0 > m0) {  // fully masked tile -> zeros; no partials
        const float4 zz = make_float4(0, 0, 0, 0);
        for (int idx = tid; idx < 128 * 32; idx += 256) {
            int row = idx >> 5, c4 = (idx & 31) << 2;
            *(float4*)&Cz[(size_t)(m0 + row) * T_ + n0 + c4] = zz;
        }
        return;
    }

    __shared__ uint32_t Ah[128][SK], Al[128][SK], Bh[128][SK], Bl[128][SK];
    __shared__ float spart[128][4];
    const int warp = tid >> 5, lane = tid & 31;
    const int wm = (warp >> 2) * 64, wn = (warp & 3) * 32;
    const int r = lane >> 2, c = lane & 3;
    const float* Ap = Q + (size_t)b * T_ * C_ + h * DH_;
    const float* Bp = Kt + (size_t)b * T_ * C_ + h * DH_;

    float4 acc[4][4];
#pragma unroll
    for (int i = 0; i < 4; i++)
#pragma unroll
        for (int j = 0; j < 4; j++) acc[i][j] = make_float4(0, 0, 0, 0);

#pragma unroll
    for (int k0 = 0; k0 < DH_; k0 += 16) {
        __syncthreads();
        load_tile128(Ap + (size_t)m0 * C_ + k0, C_, Ah, Al, tid);
        load_tile128(Bp + (size_t)n0 * C_ + k0, C_, Bh, Bl, tid);
        __syncthreads();
#pragma unroll
        for (int kb = 0; kb < 16; kb += 8) {
            uint32_t bh[4][2], bl[4][2];
#pragma unroll
            for (int nj = 0; nj < 4; nj++) {
                int col = wn + nj * 8 + r;
                bh[nj][0] = Bh[col][kb + c]; bh[nj][1] = Bh[col][kb + c + 4];
                bl[nj][0] = Bl[col][kb + c]; bl[nj][1] = Bl[col][kb + c + 4];
            }
#pragma unroll
            for (int mi = 0; mi < 4; mi++) {
                int row = wm + mi * 16 + r;
                uint32_t ah[4], al[4];
                ah[0] = Ah[row][kb + c];     ah[1] = Ah[row + 8][kb + c];
                ah[2] = Ah[row][kb + c + 4]; ah[3] = Ah[row + 8][kb + c + 4];
                al[0] = Al[row][kb + c];     al[1] = Al[row + 8][kb + c];
                al[2] = Al[row][kb + c + 4]; al[3] = Al[row + 8][kb + c + 4];
#pragma unroll
                for (int nj = 0; nj < 4; nj++) {
                    mma8(acc[mi][nj], al, bh[nj]);
                    mma8(acc[mi][nj], ah, bl[nj]);
                    mma8(acc[mi][nj], ah, bh[nj]);
                }
            }
        }
    }

    const bool diag = (n0 == m0);
#pragma unroll
    for (int mi = 0; mi < 4; mi++) {
        float se0 = 0.0f, se1 = 0.0f;
        int gm = m0 + wm + mi * 16 + r;
#pragma unroll
        for (int nj = 0; nj < 4; nj++) {
            int gn = n0 + wn + nj * 8 + 2 * c;
            float e0 = exp2f(0.125f * LOG2E * acc[mi][nj].x);
            float e1 = exp2f(0.125f * LOG2E * acc[mi][nj].y);
            float e2 = exp2f(0.125f * LOG2E * acc[mi][nj].z);
            float e3 = exp2f(0.125f * LOG2E * acc[mi][nj].w);
            if (diag) {
                if (gn > gm) e0 = 0.0f;
                if (gn + 1 > gm) e1 = 0.0f;
                if (gn > gm + 8) e2 = 0.0f;
                if (gn + 1 > gm + 8) e3 = 0.0f;
            }
            se0 += e0 + e1;
            se1 += e2 + e3;
            *(float2*)&Cz[(size_t)gm * T_ + gn]       = make_float2(e0, e1);
            *(float2*)&Cz[(size_t)(gm + 8) * T_ + gn] = make_float2(e2, e3);
        }
        se0 += __shfl_xor_sync(0xffffffffu, se0, 1);
        se0 += __shfl_xor_sync(0xffffffffu, se0, 2);
        se1 += __shfl_xor_sync(0xffffffffu, se1, 1);
        se1 += __shfl_xor_sync(0xffffffffu, se1, 2);
        if (c == 0) {
            spart[wm + mi * 16 + r][warp & 3]     = se0;
            spart[wm + mi * 16 + r + 8][warp & 3] = se1;
        }
    }
    __syncthreads();
    if (tid < 128) {
        float s = spart[tid][0] + spart[tid][1] + spart[tid][2] + spart[tid][3];
        partial[((size_t)z * T_ + m0 + tid) * 16 + (n0 >> 7)] = s;
    }
}

// ---------------------------------------------------------------------------
// Reduce partials -> 1/rowsum.
// ---------------------------------------------------------------------------
__global__ void __launch_bounds__(256) reduce_kernel(const float* __restrict__ partial,
                                                     float* __restrict__ invsum) {
    const int rg = blockIdx.x * 256 + threadIdx.x;
    const int i = rg % T_;
    const int ntmax = i >> 7;
    float s = 0.0f;
    const float* p = partial + (size_t)rg * 16;
    for (int nt = 0; nt <= ntmax; nt++) s += p[nt];
    invsum[rg] = 1.0f / s;
}

// ---------------------------------------------------------------------------
// Normalize weights in place over the valid prefix. One block (128thr) per row.
// ---------------------------------------------------------------------------
__global__ void __launch_bounds__(128) normalize_kernel(float* __restrict__ W,
                                                        const float* __restrict__ invsum) {
    const int rg = blockIdx.x;
    const int i = rg % T_;
    const int n4 = (i + 4) >> 2;   // ceil((i+1)/4) float4s (tail zeros scale to 0)
    const float il = invsum[rg];
    float4* row = (float4*)(W + (size_t)rg * T_);
    for (int j = threadIdx.x; j < n4; j += 128) {
        float4 v = row[j];
        v.x *= il; v.y *= il; v.z *= il; v.w *= il;
        row[j] = v;
    }
}

// ---------------------------------------------------------------------------
// PV k-split: plain 3xTF32 GEMM on normalized weights.
// grid (4, 16, 24): chunk ck covers k in [ck*512, min(ck*512+512, m0+128)).
// Writes partial O to g_pvpart[((z*16+mt)*4+ck)][128][64].
// ---------------------------------------------------------------------------
__global__ void __launch_bounds__(256) pv_split_tc(const float* __restrict__ W,
                                                   const float* __restrict__ V,
                                                   float* __restrict__ part) {
    const int ck = blockIdx.x, mt = blockIdx.y, z = blockIdx.z;
    const int m0 = mt * 128;
    const int kbeg = ck * 512;
    const int kend = min(kbeg + 512, m0 + 128);
    if (kbeg >= kend) return;

    const int b = z / H_, h = z % H_;
    const int tid = threadIdx.x;
    const int warp = tid >> 5, lane = tid & 31;
    const int wm = (warp >> 2) * 64, wn = (warp & 3) * 16;
    const int r = lane >> 2, c = lane & 3;

    const float* Wz = W + (size_t)z * T_ * T_;
    const float* Vp = V + (size_t)b * T_ * C_ + h * DH_;

    __shared__ uint32_t Ah[128][SK], Al[128][SK], Bh[64][SK], Bl[64][SK];

    float4 acc[4][2];
#pragma unroll
    for (int i = 0; i < 4; i++)
#pragma unroll
        for (int j = 0; j < 2; j++) acc[i][j] = make_float4(0, 0, 0, 0);

    for (int k0 = kbeg; k0 < kend; k0 += 16) {
        __syncthreads();
        load_tile128(Wz + (size_t)m0 * T_ + k0, T_, Ah, Al, tid);
        {
            int kr = tid >> 4;
            int nc = (tid & 15) << 2;
            float4 v = *(const float4*)(Vp + (size_t)(k0 + kr) * C_ + nc);
            uint32_t hh;
            hh = f2tf(v.x); Bh[nc + 0][kr] = hh; Bl[nc + 0][kr] = f2tf(v.x - __uint_as_float(hh));
            hh = f2tf(v.y); Bh[nc + 1][kr] = hh; Bl[nc + 1][kr] = f2tf(v.y - __uint_as_float(hh));
            hh = f2tf(v.z); Bh[nc + 2][kr] = hh; Bl[nc + 2][kr] = f2tf(v.z - __uint_as_float(hh));
            hh = f2tf(v.w); Bh[nc + 3][kr] = hh; Bl[nc + 3][kr] = f2tf(v.w - __uint_as_float(hh));
        }
        __syncthreads();
#pragma unroll
        for (int kb = 0; kb < 16; kb += 8) {
            uint32_t bh[2][2], bl[2][2];
#pragma unroll
            for (int nj = 0; nj < 2; nj++) {
                int col = wn + nj * 8 + r;
                bh[nj][0] = Bh[col][kb + c]; bh[nj][1] = Bh[col][kb + c + 4];
                bl[nj][0] = Bl[col][kb + c]; bl[nj][1] = Bl[col][kb + c + 4];
            }
#pragma unroll
            for (int mi = 0; mi < 4; mi++) {
                int row = wm + mi * 16 + r;
                uint32_t ah[4], al[4];
                ah[0] = Ah[row][kb + c];     ah[1] = Ah[row + 8][kb + c];
                ah[2] = Ah[row][kb + c + 4]; ah[3] = Ah[row + 8][kb + c + 4];
                al[0] = Al[row][kb + c];     al[1] = Al[row + 8][kb + c];
                al[2] = Al[row][kb + c + 4]; al[3] = Al[row + 8][kb + c + 4];
#pragma unroll
                for (int nj = 0; nj < 2; nj++) {
                    mma8(acc[mi][nj], al, bh[nj]);
                    mma8(acc[mi][nj], ah, bl[nj]);
                    mma8(acc[mi][nj], ah, bh[nj]);
                }
            }
        }
    }

    float* P = part + ((size_t)(z * 16 + mt) * 4 + ck) * (128 * DH_);
#pragma unroll
    for (int mi = 0; mi < 4; mi++)
#pragma unroll
        for (int nj = 0; nj < 2; nj++) {
            int lr = wm + mi * 16 + r;
            int gn = wn + nj * 8 + 2 * c;
            *(float2*)&P[(size_t)lr * DH_ + gn]       = make_float2(acc[mi][nj].x, acc[mi][nj].y);
            *(float2*)&P[(size_t)(lr + 8) * DH_ + gn] = make_float2(acc[mi][nj].z, acc[mi][nj].w);
        }
}

// ---------------------------------------------------------------------------
// Sum pv partials -> O (g_att layout [B,T,C]). grid (384), 256 thr.
// ---------------------------------------------------------------------------
__global__ void __launch_bounds__(256) pv_reduce(const float* __restrict__ part,
                                                 float* __restrict__ O) {
    const int blk = blockIdx.x;            // z*16 + mt
    const int z = blk >> 4, mt = blk & 15;
    const int b = z / H_, h = z % H_;
    const int m0 = mt * 128;
    const int nch = (mt >> 2) + 1;         // ceil((mt+1)*128/512)
    const float* p = part + (size_t)blk * 4 * (128 * DH_);

    for (int idx = threadIdx.x * 4; idx < 128 * DH_; idx += 256 * 4) {
        float4 s = *(const float4*)(p + idx);
        for (int c2 = 1; c2 < nch; c2++) {
            float4 t = *(const float4*)(p + (size_t)c2 * 128 * DH_ + idx);
            s.x += t.x; s.y += t.y; s.z += t.z; s.w += t.w;
        }
        const int row = idx >> 6, n = idx & 63;
        *(float4*)&O[(size_t)(b * T_ + m0 + row) * C_ + h * DH_ + n] = s;
    }
}

// ---------------------------------------------------------------------------
extern "C" void kernel_launch(void* const* d_in, const int* in_sizes, int n_in,
                              void* d_out, int out_size) {
    const float* x   = (const float*)d_in[0];
    const float* w_q = (const float*)d_in[1];
    const float* w_k = (const float*)d_in[2];
    const float* w_v = (const float*)d_in[3];
    const float* w_o = (const float*)d_in[4];

    float* qp; cudaGetSymbolAddress((void**)&qp, g_q);
    float* kp; cudaGetSymbolAddress((void**)&kp, g_k);
    float* vp; cudaGetSymbolAddress((void**)&vp, g_v);
    float* ap; cudaGetSymbolAddress((void**)&ap, g_att);
    float* pp; cudaGetSymbolAddress((void**)&pp, g_partial);
    float* ip; cudaGetSymbolAddress((void**)&ip, g_invsum);
    float* vv; cudaGetSymbolAddress((void**)&vv, g_pvpart);

    float* final_out = (float*)d_out;                       // [B,T,C]
    float* w_out = (float*)d_out + (size_t)B_ * T_ * C_;    // [B,H,T,T]

    const dim3 blk(256);

    gemm_qkv<<<dim3(18, 32), blk>>>(x, w_q, w_k, w_v, qp, kp, vp);

    scores_tc<<<dim3(T_ / 128, T_ / 128, B_ * H_), blk>>>(qp, kp, w_out, pp);

    reduce_kernel<<<(B_ * H_ * T_) / 256, blk>>>(pp, ip);

    normalize_kernel<<<B_ * H_ * T_, 128>>>(w_out, ip);

    pv_split_tc<<<dim3(4, 16, 24), blk>>>(w_out, vp, vv);

    pv_reduce<<<B_ * H_ * 16, blk>>>(vv, ap);

    gemm_final<<<dim3(6, 32), blk>>>(ap, w_o, final_out);
}